// round 7
// baseline (speedup 1.0000x reference)
#include <cuda_runtime.h>
#include <cuda_bf16.h>
#include <cuda_fp16.h>

// ---------------------------------------------------------------------------
// Turbo decoder (linear-domain BCJR), 8-state RSC, B=256, K=6144, 6 iters.
// Fused sliding-window BCJR (L=32, W=32). Each thread carries TWO independent
// b-chains (b = 2*lane+{0,1}, float2 I/O) for ILP; beta tiles in SMEM (half2).
// Power-of-two normalization (exponent trick) keeps state sums in [1,2).
// All LLR arrays stored HALF-SCALE (x0.5) and negated; time-major [t][B].
// ---------------------------------------------------------------------------

constexpr int Kc = 6144;
constexpr int Bc = 256;
constexpr int Lc = 32;
constexpr int Wc = 32;
constexpr int Cc = Kc / Lc;   // 192 chunks

// Static device scratch (no allocations anywhere).
__device__ float g_ls1[Kc * Bc];
__device__ float g_lp1[Kc * Bc];
__device__ float g_lp2[Kc * Bc];
__device__ float g_ls2[Kc * Bc];
__device__ float g_la1[Kc * Bc];
__device__ float g_la2[Kc * Bc];
__device__ float g_lpost[Kc * Bc];
__device__ int   g_inv[Kc];

// r = 2^-(ilogb(s)) : one LOP + one IADD on the exponent field. s in normal
// range is guaranteed (sum >= e^-60 per step given the m-offset below).
__device__ __forceinline__ float norm_scale(float s) {
    return __uint_as_float(0x7F000000u - (__float_as_uint(s) & 0x7F800000u));
}

// Branch probabilities; inputs are half-scale LLRs: g0 = ls'+la'+lp',
// g1 = ls'+la'-lp' (i.e. the original 0.5*(...) values). Offset by m so all
// exp args <= 0; the e^-m scale cancels in normalization & posterior ratio.
__device__ __forceinline__ void branch_probs(float lsv, float lav, float lpv,
                                             float (&e)[4]) {
    float h  = lsv + lav;
    float g0 = h + lpv, g1 = h - lpv;
    float m  = fminf(fmaxf(fabsf(g0), fabsf(g1)), 60.0f);
    e[0] = __expf(g0 - m);  e[1] = __expf(-g0 - m);   // e0p, e0n
    e[2] = __expf(g1 - m);  e[3] = __expf(-g1 - m);   // e1p, e1n
}

// Trellis (G0=(1,0,1,1), G1=(1,1,0,1), MU=3):
//   branch prob for (s,u=0) is e0p for s in {0,1,6,7}, e1p for s in {2,3,4,5};
//   u=1 uses the matching e*n. next: 0:(0,4) 1:(4,0) 2:(5,1) 3:(1,5)
//   4:(2,6) 5:(6,2) 6:(7,3) 7:(3,7)

__device__ __forceinline__ void fwd_step_lin(const float (&e)[4], float (&a)[8]) {
    float n0 = a[0]*e[0] + a[1]*e[1];
    float n4 = a[0]*e[1] + a[1]*e[0];
    float n5 = a[2]*e[2] + a[3]*e[3];
    float n1 = a[2]*e[3] + a[3]*e[2];
    float n2 = a[4]*e[2] + a[5]*e[3];
    float n6 = a[4]*e[3] + a[5]*e[2];
    float n7 = a[6]*e[0] + a[7]*e[1];
    float n3 = a[6]*e[1] + a[7]*e[0];
    float s  = ((n0+n1)+(n2+n3)) + ((n4+n5)+(n6+n7));
    float r  = norm_scale(s);
    a[0]=n0*r; a[1]=n1*r; a[2]=n2*r; a[3]=n3*r;
    a[4]=n4*r; a[5]=n5*r; a[6]=n6*r; a[7]=n7*r;
}

__device__ __forceinline__ void bwd_step_lin(const float (&e)[4], float (&B)[8]) {
    float n0 = B[0]*e[0] + B[4]*e[1];
    float n1 = B[4]*e[0] + B[0]*e[1];
    float n2 = B[5]*e[2] + B[1]*e[3];
    float n3 = B[1]*e[2] + B[5]*e[3];
    float n4 = B[2]*e[2] + B[6]*e[3];
    float n5 = B[6]*e[2] + B[2]*e[3];
    float n6 = B[7]*e[0] + B[3]*e[1];
    float n7 = B[3]*e[0] + B[7]*e[1];
    float s  = ((n0+n1)+(n2+n3)) + ((n4+n5)+(n6+n7));
    float r  = norm_scale(s);
    B[0]=n0*r; B[1]=n1*r; B[2]=n2*r; B[3]=n3*r;
    B[4]=n4*r; B[5]=n5*r; B[6]=n6*r; B[7]=n7*r;
}

// ---------------------------------------------------------------------------
// Setup kernels
// ---------------------------------------------------------------------------
__global__ void unpack_kernel(const float* __restrict__ in) {
    // in: [B][3K] row-major; produce time-major HALF-SCALE negated LLRs.
    // Also zeroes g_la1 for iteration 0.
    __shared__ float tile[3][32][33];
    int t0 = blockIdx.x * 32;
    int b0 = blockIdx.y * 32;
    int tid = threadIdx.x;
    for (int e = tid; e < 32 * 96; e += 256) {
        int db  = e / 96;
        int off = e % 96;
        float v = in[(size_t)(b0 + db) * (3 * Kc) + 3 * t0 + off];
        tile[off % 3][off / 3][db] = -0.5f * v;
    }
    __syncthreads();
    for (int e = tid; e < 3 * 32 * 32; e += 256) {
        int cc = e >> 10;
        int r  = e & 1023;
        int tt = r >> 5;
        int bb = r & 31;
        float v = tile[cc][tt][bb];
        float* dst = (cc == 0) ? g_ls1 : (cc == 1) ? g_lp1 : g_lp2;
        dst[(t0 + tt) * Bc + b0 + bb] = v;
    }
    for (int e = tid; e < 1024; e += 256) {
        int tt = e >> 5, bb = e & 31;
        g_la1[(t0 + tt) * Bc + b0 + bb] = 0.0f;
    }
}

__global__ void build_inv_kernel(const int* __restrict__ perm) {
    int j = blockIdx.x * 256 + threadIdx.x;
    if (j < Kc) g_inv[perm[j]] = j;
}

__global__ void gather_ls2_kernel(const int* __restrict__ perm) {
    // ls2[j][b] = ls1[perm[j]][b]
    int b  = threadIdx.x;
    int j0 = blockIdx.x * 8;
    #pragma unroll
    for (int r = 0; r < 8; ++r)
        g_ls2[(j0 + r) * Bc + b] = g_ls1[perm[j0 + r] * Bc + b];
}

// ---------------------------------------------------------------------------
// Fused BCJR pass (one decoder half-iteration), linear domain, 2 b-chains
// per thread. dec==0: reads la1, writes g_la2[inv[t]]; dec==1: reads la2,
// writes g_la1[perm[t]]. last!=0: also store lpost' (half-scale, time-major).
// ---------------------------------------------------------------------------
__global__ void __launch_bounds__(32) bcjr_pass(int dec, const int* __restrict__ perm, int last) {
    __shared__ __half2 sbeta[Lc * 8 * 32];   // [t_rel][chain*4+pair][lane], 32 KB

    const float2* __restrict__ ls = (const float2*)(dec ? g_ls2 : g_ls1);
    const float2* __restrict__ lp = (const float2*)(dec ? g_lp2 : g_lp1);
    const float2* __restrict__ la = (const float2*)(dec ? g_la2 : g_la1);
    float2* __restrict__ lout     = (float2*)(dec ? g_la1 : g_la2);
    float2* __restrict__ lpo      = (float2*)g_lpost;
    const int* __restrict__ map   = dec ? perm : g_inv;

    const int lane = threadIdx.x;
    const int boff = blockIdx.y * 32 + lane;    // float2 index within a row
    const int c    = blockIdx.x;
    const int t_lo = c * Lc;
    const int t_sh = t_lo + Lc - 1;
    constexpr int RW = Bc / 2;                  // 128 float2 per row

    // ---------------- backward ----------------
    {
        int t_hi = t_lo + Lc + Wc - 1;
        if (t_hi > Kc - 1) t_hi = Kc - 1;       // clamp: uniform init == exact beta_K

        float B0[8], B1[8];
        #pragma unroll
        for (int s = 0; s < 8; ++s) { B0[s] = 0.125f; B1[s] = 0.125f; }

        #pragma unroll 2
        for (int t = t_hi; t > t_sh; --t) {     // warmup (no stores)
            int idx = t * RW + boff;
            float2 lsv = ls[idx], lav = la[idx], lpv = lp[idx];
            float e0[4], e1[4];
            branch_probs(lsv.x, lav.x, lpv.x, e0);
            branch_probs(lsv.y, lav.y, lpv.y, e1);
            bwd_step_lin(e0, B0);
            bwd_step_lin(e1, B1);
        }
        #pragma unroll 2
        for (int t = t_sh; t >= t_lo; --t) {    // main region -> SMEM
            __half2* p = &sbeta[(t - t_lo) * 256 + lane];
            p[0]   = __floats2half2_rn(B0[0], B0[1]);
            p[32]  = __floats2half2_rn(B0[2], B0[3]);
            p[64]  = __floats2half2_rn(B0[4], B0[5]);
            p[96]  = __floats2half2_rn(B0[6], B0[7]);
            p[128] = __floats2half2_rn(B1[0], B1[1]);
            p[160] = __floats2half2_rn(B1[2], B1[3]);
            p[192] = __floats2half2_rn(B1[4], B1[5]);
            p[224] = __floats2half2_rn(B1[6], B1[7]);
            int idx = t * RW + boff;
            float2 lsv = ls[idx], lav = la[idx], lpv = lp[idx];
            float e0[4], e1[4];
            branch_probs(lsv.x, lav.x, lpv.x, e0);
            branch_probs(lsv.y, lav.y, lpv.y, e1);
            bwd_step_lin(e0, B0);
            bwd_step_lin(e1, B1);
        }
    }

    // ---------------- forward + posterior ----------------
    {
        int t0 = t_lo - Wc; if (t0 < 0) t0 = 0;

        float A0[8], A1[8];
        if (t0 == 0) {                           // exact init: state 0
            #pragma unroll
            for (int s = 0; s < 8; ++s) { A0[s] = 0.0f; A1[s] = 0.0f; }
            A0[0] = 1.0f; A1[0] = 1.0f;
        } else {
            #pragma unroll
            for (int s = 0; s < 8; ++s) { A0[s] = 0.125f; A1[s] = 0.125f; }
        }

        #pragma unroll 2
        for (int t = t0; t < t_lo; ++t) {        // warmup
            int idx = t * RW + boff;
            float2 lsv = ls[idx], lav = la[idx], lpv = lp[idx];
            float e0[4], e1[4];
            branch_probs(lsv.x, lav.x, lpv.x, e0);
            branch_probs(lsv.y, lav.y, lpv.y, e1);
            fwd_step_lin(e0, A0);
            fwd_step_lin(e1, A1);
        }

        #pragma unroll 2
        for (int t = t_lo; t <= t_sh; ++t) {     // main region
            int idx = t * RW + boff;
            float2 lsv = ls[idx], lav = la[idx], lpv = lp[idx];
            float e0[4], e1[4];
            branch_probs(lsv.x, lav.x, lpv.x, e0);
            branch_probs(lsv.y, lav.y, lpv.y, e1);

            const __half2* p = &sbeta[(t - t_lo) * 256 + lane];
            float2 lps;
            {   // chain 0
                float2 q01 = __half22float2(p[0]);
                float2 q23 = __half22float2(p[32]);
                float2 q45 = __half22float2(p[64]);
                float2 q67 = __half22float2(p[96]);
                // u_k = sum_s alpha[s] * p(s,u=k) * beta[nxt(s,k)]
                float u0 = e0[0] * (A0[0]*q01.x + A0[1]*q45.x + A0[6]*q67.y + A0[7]*q23.y)
                         + e0[2] * (A0[2]*q45.y + A0[3]*q01.y + A0[4]*q23.x + A0[5]*q67.x);
                float u1 = e0[1] * (A0[0]*q45.x + A0[1]*q01.x + A0[6]*q23.y + A0[7]*q67.y)
                         + e0[3] * (A0[2]*q01.y + A0[3]*q45.y + A0[4]*q67.x + A0[5]*q23.x);
                lps.x = 0.5f * (__logf(fmaxf(u0, 1e-38f)) - __logf(fmaxf(u1, 1e-38f)));
            }
            {   // chain 1
                float2 q01 = __half22float2(p[128]);
                float2 q23 = __half22float2(p[160]);
                float2 q45 = __half22float2(p[192]);
                float2 q67 = __half22float2(p[224]);
                float u0 = e1[0] * (A1[0]*q01.x + A1[1]*q45.x + A1[6]*q67.y + A1[7]*q23.y)
                         + e1[2] * (A1[2]*q45.y + A1[3]*q01.y + A1[4]*q23.x + A1[5]*q67.x);
                float u1 = e1[1] * (A1[0]*q45.x + A1[1]*q01.x + A1[6]*q23.y + A1[7]*q67.y)
                         + e1[3] * (A1[2]*q01.y + A1[3]*q45.y + A1[4]*q67.x + A1[5]*q23.x);
                lps.y = 0.5f * (__logf(fmaxf(u0, 1e-38f)) - __logf(fmaxf(u1, 1e-38f)));
            }

            float2 ext;   // half-scale extrinsic = lpost' - la' - ls'
            ext.x = lps.x - lav.x - lsv.x;
            ext.y = lps.y - lav.y - lsv.y;
            lout[map[t] * RW + boff] = ext;
            if (last) lpo[idx] = lps;

            fwd_step_lin(e0, A0);
            fwd_step_lin(e1, A1);
        }
    }
}

// ---------------------------------------------------------------------------
// Output: out[b][i] = -lpost2_full[inv[i]][b] = -2 * lpost'[inv[i]][b]
// ---------------------------------------------------------------------------
__global__ void output_kernel(float* __restrict__ out) {
    __shared__ float tile[32][33];
    int i0 = blockIdx.x * 32, b0 = blockIdx.y * 32;
    int tid = threadIdx.x;
    for (int e = tid; e < 1024; e += 256) {
        int ii = e >> 5, bb = e & 31;
        tile[ii][bb] = -2.0f * g_lpost[g_inv[i0 + ii] * Bc + b0 + bb];
    }
    __syncthreads();
    for (int e = tid; e < 1024; e += 256) {
        int bb = e >> 5, ii = e & 31;
        out[(size_t)(b0 + bb) * Kc + i0 + ii] = tile[ii][bb];
    }
}

// ---------------------------------------------------------------------------
extern "C" void kernel_launch(void* const* d_in, const int* in_sizes, int n_in,
                              void* d_out, int out_size) {
    const float* in  = (const float*)d_in[0];
    const int* perm  = (const int*)d_in[1];
    float* out       = (float*)d_out;

    dim3 upg(Kc / 32, Bc / 32);
    unpack_kernel<<<upg, 256>>>(in);
    build_inv_kernel<<<Kc / 256, 256>>>(perm);
    gather_ls2_kernel<<<Kc / 8, 256>>>(perm);

    dim3 bg(Cc, Bc / 64);   // 192 x 4 one-warp blocks, 2 b-chains per thread
    for (int it = 0; it < 6; ++it) {
        bcjr_pass<<<bg, 32>>>(0, perm, 0);
        bcjr_pass<<<bg, 32>>>(1, perm, (it == 5) ? 1 : 0);
    }

    dim3 og(Kc / 32, Bc / 32);
    output_kernel<<<og, 256>>>(out);
}

// round 8
// speedup vs baseline: 1.2502x; 1.2502x over previous
#include <cuda_runtime.h>
#include <cuda_bf16.h>
#include <cuda_fp16.h>

// ---------------------------------------------------------------------------
// Turbo decoder (linear-domain BCJR in log2 units), 8-state RSC,
// B=256, K=6144, 6 iterations. Sliding-window (L=32, W=32).
// Per chunk: one 64-thread block; warp0 runs the backward recursion (beta ->
// SMEM as half2), warp1 runs the forward warmup concurrently, then after one
// barrier the forward main loop + posterior + extrinsic scatter.
// All LLR arrays stored scaled by 0.5*log2(e) and negated; time-major [t][B].
// ---------------------------------------------------------------------------

constexpr int Kc = 6144;
constexpr int Bc = 256;
constexpr int Lc = 32;
constexpr int Wc = 32;
constexpr int Cc = Kc / Lc;           // 192 chunks
constexpr float SCALEF   = 0.7213475204444817f;   // 0.5*log2(e)
constexpr float OUTSCALE = -1.3862943611198906f;  // -2*ln2  (undo SCALEF, negate)
constexpr float GCLAMP   = 50.0f;                 // log2-unit branch clamp

// Static device scratch (no allocations anywhere).
__device__ float g_ls1[Kc * Bc];
__device__ float g_lp1[Kc * Bc];
__device__ float g_lp2[Kc * Bc];
__device__ float g_ls2[Kc * Bc];
__device__ float g_la1[Kc * Bc];
__device__ float g_la2[Kc * Bc];
__device__ float g_lpost[Kc * Bc];
__device__ int   g_inv[Kc];

__device__ __forceinline__ float ex2f(float x) {
    float y; asm("ex2.approx.ftz.f32 %0, %1;" : "=f"(y) : "f"(x)); return y;
}
__device__ __forceinline__ float lg2f(float x) {
    float y; asm("lg2.approx.ftz.f32 %0, %1;" : "=f"(y) : "f"(x)); return y;
}

// r = 2^-(ilogb(s)) : exponent-field trick, no MUFU.
__device__ __forceinline__ float norm_scale(float s) {
    return __uint_as_float(0x7F000000u - (__float_as_uint(s) & 0x7F800000u));
}

// Branch weights 2^{±g0}, 2^{±g1} with g0 = ls'+la'+lp', g1 = ls'+la'-lp'
// (log2-scaled units). Clamped so every-2-step normalization cannot overflow.
__device__ __forceinline__ void branch_w(float lsv, float lav, float lpv,
                                         float (&e)[4]) {
    float h  = lsv + lav;
    float g0 = fminf(fmaxf(h + lpv, -GCLAMP), GCLAMP);
    float g1 = fminf(fmaxf(h - lpv, -GCLAMP), GCLAMP);
    e[0] = ex2f(g0);  e[1] = ex2f(-g0);   // e0p, e0n
    e[2] = ex2f(g1);  e[3] = ex2f(-g1);   // e1p, e1n
}

// Trellis (G0=(1,0,1,1), G1=(1,1,0,1), MU=3):
//   weight(s,u=0) = e0p for s in {0,1,6,7}, e1p for s in {2,3,4,5}; u=1 -> e*n.
//   next: 0:(0,4) 1:(4,0) 2:(5,1) 3:(1,5) 4:(2,6) 5:(6,2) 6:(7,3) 7:(3,7)

__device__ __forceinline__ void norm8(float (&v)[8]) {
    float s = ((v[0]+v[1])+(v[2]+v[3])) + ((v[4]+v[5])+(v[6]+v[7]));
    float r = norm_scale(s);
    #pragma unroll
    for (int i = 0; i < 8; ++i) v[i] *= r;
}

__device__ __forceinline__ void fwd_step(const float (&e)[4], float (&a)[8]) {
    float n0 = a[0]*e[0] + a[1]*e[1];
    float n4 = a[0]*e[1] + a[1]*e[0];
    float n5 = a[2]*e[2] + a[3]*e[3];
    float n1 = a[2]*e[3] + a[3]*e[2];
    float n2 = a[4]*e[2] + a[5]*e[3];
    float n6 = a[4]*e[3] + a[5]*e[2];
    float n7 = a[6]*e[0] + a[7]*e[1];
    float n3 = a[6]*e[1] + a[7]*e[0];
    a[0]=n0; a[1]=n1; a[2]=n2; a[3]=n3; a[4]=n4; a[5]=n5; a[6]=n6; a[7]=n7;
}

__device__ __forceinline__ void bwd_step(const float (&e)[4], float (&B)[8]) {
    float n0 = B[0]*e[0] + B[4]*e[1];
    float n1 = B[4]*e[0] + B[0]*e[1];
    float n2 = B[5]*e[2] + B[1]*e[3];
    float n3 = B[1]*e[2] + B[5]*e[3];
    float n4 = B[2]*e[2] + B[6]*e[3];
    float n5 = B[6]*e[2] + B[2]*e[3];
    float n6 = B[7]*e[0] + B[3]*e[1];
    float n7 = B[3]*e[0] + B[7]*e[1];
    B[0]=n0; B[1]=n1; B[2]=n2; B[3]=n3; B[4]=n4; B[5]=n5; B[6]=n6; B[7]=n7;
}

// ---------------------------------------------------------------------------
// Setup kernels
// ---------------------------------------------------------------------------
__global__ void unpack_kernel(const float* __restrict__ in) {
    // in: [B][3K]; produce time-major, negated, 0.5*log2(e)-scaled LLRs.
    // Also zeroes g_la1 for iteration 0.
    __shared__ float tile[3][32][33];
    int t0 = blockIdx.x * 32;
    int b0 = blockIdx.y * 32;
    int tid = threadIdx.x;
    for (int e = tid; e < 32 * 96; e += 256) {
        int db  = e / 96;
        int off = e % 96;
        float v = in[(size_t)(b0 + db) * (3 * Kc) + 3 * t0 + off];
        tile[off % 3][off / 3][db] = -SCALEF * v;
    }
    __syncthreads();
    for (int e = tid; e < 3 * 32 * 32; e += 256) {
        int cc = e >> 10;
        int r  = e & 1023;
        int tt = r >> 5;
        int bb = r & 31;
        float v = tile[cc][tt][bb];
        float* dst = (cc == 0) ? g_ls1 : (cc == 1) ? g_lp1 : g_lp2;
        dst[(t0 + tt) * Bc + b0 + bb] = v;
    }
    for (int e = tid; e < 1024; e += 256) {
        int tt = e >> 5, bb = e & 31;
        g_la1[(t0 + tt) * Bc + b0 + bb] = 0.0f;
    }
}

__global__ void build_inv_kernel(const int* __restrict__ perm) {
    int j = blockIdx.x * 256 + threadIdx.x;
    if (j < Kc) g_inv[perm[j]] = j;
}

__global__ void gather_ls2_kernel(const int* __restrict__ perm) {
    int b  = threadIdx.x;
    int j0 = blockIdx.x * 8;
    #pragma unroll
    for (int r = 0; r < 8; ++r)
        g_ls2[(j0 + r) * Bc + b] = g_ls1[perm[j0 + r] * Bc + b];
}

// ---------------------------------------------------------------------------
// Fused BCJR pass, two warps per block (warp0 = backward, warp1 = forward).
//   dec==0: reads la1, writes g_la2[inv[t]] = lpost' - la' - ls'
//   dec==1: reads la2, writes g_la1[perm[t]] = lpost' - la' - ls'
//   last!=0: also store lpost' (time-major) for the final output transpose.
// ---------------------------------------------------------------------------
__global__ void __launch_bounds__(64) bcjr_pass(int dec, const int* __restrict__ perm, int last) {
    // beta_{t+1} per (t_rel, lane): 8 states as 4 half2 packed in one uint4.
    __shared__ uint4 sbeta[Lc][32];

    const float* __restrict__ ls = dec ? g_ls2 : g_ls1;
    const float* __restrict__ lp = dec ? g_lp2 : g_lp1;
    const float* __restrict__ la = dec ? g_la2 : g_la1;
    float* __restrict__ lout     = dec ? g_la1 : g_la2;
    const int* __restrict__ map  = dec ? perm : g_inv;

    const int lane = threadIdx.x & 31;
    const int wid  = threadIdx.x >> 5;
    const int b    = blockIdx.y * 32 + lane;
    const int c    = blockIdx.x;
    const int t_lo = c * Lc;
    const int t_sh = t_lo + Lc - 1;

    if (wid == 0) {
        // ---------------- backward warp ----------------
        int t_hi = t_sh + Wc;
        if (t_hi > Kc - 1) t_hi = Kc - 1;   // c==191: 0 warmup (uniform == exact beta_K)

        float B[8];
        #pragma unroll
        for (int s = 0; s < 8; ++s) B[s] = 0.125f;

        // warmup: pairs, normalize once per pair (step count is 32 or 0)
        for (int t = t_hi; t > t_sh; t -= 2) {
            float e[4];
            int idx = t * Bc + b;
            branch_w(ls[idx], la[idx], lp[idx], e);
            bwd_step(e, B);
            idx -= Bc;
            branch_w(ls[idx], la[idx], lp[idx], e);
            bwd_step(e, B);
            norm8(B);
        }
        // main region: store normalized beta_{t+1}, then step+norm
        #pragma unroll 2
        for (int t = t_sh; t >= t_lo; --t) {
            __half2 h01 = __floats2half2_rn(B[0], B[1]);
            __half2 h23 = __floats2half2_rn(B[2], B[3]);
            __half2 h45 = __floats2half2_rn(B[4], B[5]);
            __half2 h67 = __floats2half2_rn(B[6], B[7]);
            uint4 pk;
            pk.x = reinterpret_cast<unsigned&>(h01);
            pk.y = reinterpret_cast<unsigned&>(h23);
            pk.z = reinterpret_cast<unsigned&>(h45);
            pk.w = reinterpret_cast<unsigned&>(h67);
            sbeta[t - t_lo][lane] = pk;

            float e[4];
            int idx = t * Bc + b;
            branch_w(ls[idx], la[idx], lp[idx], e);
            bwd_step(e, B);
            norm8(B);
        }
    } else {
        // ---------------- forward warp: warmup only (runs concurrently) ----
        int t0 = t_lo - Wc; if (t0 < 0) t0 = 0;
        float A[8];
        if (t0 == 0) {                       // exact init: state 0
            #pragma unroll
            for (int s = 0; s < 8; ++s) A[s] = 0.0f;
            A[0] = 1.0f;
        } else {
            #pragma unroll
            for (int s = 0; s < 8; ++s) A[s] = 0.125f;
        }
        for (int t = t0; t < t_lo; t += 2) { // step count is 32 or 0
            float e[4];
            int idx = t * Bc + b;
            branch_w(ls[idx], la[idx], lp[idx], e);
            fwd_step(e, A);
            idx += Bc;
            branch_w(ls[idx], la[idx], lp[idx], e);
            fwd_step(e, A);
            norm8(A);
        }
        // stash alpha in shared? No — keep in registers across the barrier.
        // (registers are per-thread; barrier does not disturb them)
        // main loop below.
        __syncthreads();

        #pragma unroll 2
        for (int t = t_lo; t <= t_sh; ++t) {
            int idx = t * Bc + b;
            float lsv = ls[idx], lav = la[idx], lpv = lp[idx];
            float e[4];
            branch_w(lsv, lav, lpv, e);

            uint4 pk = sbeta[t - t_lo][lane];
            float2 q01 = __half22float2(reinterpret_cast<__half2&>(pk.x));
            float2 q23 = __half22float2(reinterpret_cast<__half2&>(pk.y));
            float2 q45 = __half22float2(reinterpret_cast<__half2&>(pk.z));
            float2 q67 = __half22float2(reinterpret_cast<__half2&>(pk.w));

            // u_k = sum_s alpha[s] * w(s,u=k) * beta_{t+1}[nxt(s,k)]
            float u0 = e[0] * (A[0]*q01.x + A[1]*q45.x + A[6]*q67.y + A[7]*q23.y)
                     + e[2] * (A[2]*q45.y + A[3]*q01.y + A[4]*q23.x + A[5]*q67.x);
            float u1 = e[1] * (A[0]*q45.x + A[1]*q01.x + A[6]*q23.y + A[7]*q67.y)
                     + e[3] * (A[2]*q01.y + A[3]*q45.y + A[4]*q67.x + A[5]*q23.x);
            float lps = 0.5f * (lg2f(fmaxf(u0, 1e-30f)) - lg2f(fmaxf(u1, 1e-30f)));

            lout[map[t] * Bc + b] = lps - lav - lsv;
            if (last) g_lpost[idx] = lps;

            fwd_step(e, A);
            if ((t - t_lo) & 1) norm8(A);    // normalize every 2nd step
        }
        return;
    }
    __syncthreads();   // bwd warp arrives here after filling sbeta
}

// ---------------------------------------------------------------------------
// Output: out[b][i] = -2*ln2 * lpost'[inv[i]][b]
// ---------------------------------------------------------------------------
__global__ void output_kernel(float* __restrict__ out) {
    __shared__ float tile[32][33];
    int i0 = blockIdx.x * 32, b0 = blockIdx.y * 32;
    int tid = threadIdx.x;
    for (int e = tid; e < 1024; e += 256) {
        int ii = e >> 5, bb = e & 31;
        tile[ii][bb] = OUTSCALE * g_lpost[g_inv[i0 + ii] * Bc + b0 + bb];
    }
    __syncthreads();
    for (int e = tid; e < 1024; e += 256) {
        int bb = e >> 5, ii = e & 31;
        out[(size_t)(b0 + bb) * Kc + i0 + ii] = tile[ii][bb];
    }
}

// ---------------------------------------------------------------------------
extern "C" void kernel_launch(void* const* d_in, const int* in_sizes, int n_in,
                              void* d_out, int out_size) {
    const float* in  = (const float*)d_in[0];
    const int* perm  = (const int*)d_in[1];
    float* out       = (float*)d_out;

    dim3 upg(Kc / 32, Bc / 32);
    unpack_kernel<<<upg, 256>>>(in);
    build_inv_kernel<<<Kc / 256, 256>>>(perm);
    gather_ls2_kernel<<<Kc / 8, 256>>>(perm);

    dim3 bg(Cc, Bc / 32);   // 192 x 8 blocks, 2 warps each -> 3072 warps
    for (int it = 0; it < 6; ++it) {
        bcjr_pass<<<bg, 64>>>(0, perm, 0);
        bcjr_pass<<<bg, 64>>>(1, perm, (it == 5) ? 1 : 0);
    }

    dim3 og(Kc / 32, Bc / 32);
    output_kernel<<<og, 256>>>(out);
}

// round 9
// speedup vs baseline: 1.3614x; 1.0890x over previous
#include <cuda_runtime.h>
#include <cuda_bf16.h>
#include <cuda_fp16.h>

// ---------------------------------------------------------------------------
// Turbo decoder (linear-domain BCJR in log2 units), 8-state RSC,
// B=256, K=6144, 6 iterations. Sliding-window (L=32, W=32).
// Branch metrics are PRE-COMBINED: G[t][b] = (g0', g1') float2 where
// g0' = (ls+la+lp)*0.5*log2e, g1' = (ls+la-lp)*0.5*log2e. Each BCJR pass
// reads ONE float2 per step and writes the NEXT pass's G directly through
// the interleaver using the iteration-invariant S = ls'+lp', D = ls'-lp'.
// Per chunk: 64-thread block; warp0 = backward (beta -> SMEM half2x4),
// warp1 = forward warmup (concurrent) then forward main + posterior.
// ---------------------------------------------------------------------------

constexpr int Kc = 6144;
constexpr int Bc = 256;
constexpr int Lc = 32;
constexpr int Wc = 32;
constexpr int Cc = Kc / Lc;           // 192 chunks
constexpr float SCALEF   = 0.7213475204444817f;   // 0.5*log2(e)
constexpr float OUTSCALE = -1.3862943611198906f;  // -2*ln2  (undo SCALEF, negate)
constexpr float GCLAMP   = 60.0f;                 // log2-unit branch clamp

// Static device scratch (no allocations anywhere).
__device__ float  g_ls1[Kc * Bc];     // scaled, negated systematic (dec1 order)
__device__ float  g_lp2[Kc * Bc];     // scaled, negated parity 2 (dec2 order)
__device__ float  g_S1[Kc * Bc];      // ls1' + lp1'
__device__ float  g_D1[Kc * Bc];      // ls1' - lp1'
__device__ float  g_S2[Kc * Bc];      // ls2' + lp2'
__device__ float  g_D2[Kc * Bc];      // ls2' - lp2'
__device__ float2 g_G1[Kc * Bc];      // branch metrics for decoder 1
__device__ float2 g_G2[Kc * Bc];      // branch metrics for decoder 2
__device__ float  g_lpost[Kc * Bc];
__device__ int    g_inv[Kc];

__device__ __forceinline__ float ex2f(float x) {
    float y; asm("ex2.approx.ftz.f32 %0, %1;" : "=f"(y) : "f"(x)); return y;
}
__device__ __forceinline__ float lg2f(float x) {
    float y; asm("lg2.approx.ftz.f32 %0, %1;" : "=f"(y) : "f"(x)); return y;
}

// r = 2^-(ilogb(s)) : exponent-field trick, no MUFU.
__device__ __forceinline__ float norm_scale(float s) {
    return __uint_as_float(0x7F000000u - (__float_as_uint(s) & 0x7F800000u));
}

__device__ __forceinline__ void weights(float2 g, float (&e)[4]) {
    e[0] = ex2f(g.x);  e[1] = ex2f(-g.x);   // e0p, e0n
    e[2] = ex2f(g.y);  e[3] = ex2f(-g.y);   // e1p, e1n
}

// Trellis (G0=(1,0,1,1), G1=(1,1,0,1), MU=3):
//   weight(s,u=0) = e0p for s in {0,1,6,7}, e1p for s in {2,3,4,5}; u=1 -> e*n.
//   next: 0:(0,4) 1:(4,0) 2:(5,1) 3:(1,5) 4:(2,6) 5:(6,2) 6:(7,3) 7:(3,7)

__device__ __forceinline__ void norm8(float (&v)[8]) {
    float s = ((v[0]+v[1])+(v[2]+v[3])) + ((v[4]+v[5])+(v[6]+v[7]));
    float r = norm_scale(s);
    #pragma unroll
    for (int i = 0; i < 8; ++i) v[i] *= r;
}

__device__ __forceinline__ void fwd_step(const float (&e)[4], float (&a)[8]) {
    float n0 = a[0]*e[0] + a[1]*e[1];
    float n4 = a[0]*e[1] + a[1]*e[0];
    float n5 = a[2]*e[2] + a[3]*e[3];
    float n1 = a[2]*e[3] + a[3]*e[2];
    float n2 = a[4]*e[2] + a[5]*e[3];
    float n6 = a[4]*e[3] + a[5]*e[2];
    float n7 = a[6]*e[0] + a[7]*e[1];
    float n3 = a[6]*e[1] + a[7]*e[0];
    a[0]=n0; a[1]=n1; a[2]=n2; a[3]=n3; a[4]=n4; a[5]=n5; a[6]=n6; a[7]=n7;
}

__device__ __forceinline__ void bwd_step(const float (&e)[4], float (&B)[8]) {
    float n0 = B[0]*e[0] + B[4]*e[1];
    float n1 = B[4]*e[0] + B[0]*e[1];
    float n2 = B[5]*e[2] + B[1]*e[3];
    float n3 = B[1]*e[2] + B[5]*e[3];
    float n4 = B[2]*e[2] + B[6]*e[3];
    float n5 = B[6]*e[2] + B[2]*e[3];
    float n6 = B[7]*e[0] + B[3]*e[1];
    float n7 = B[3]*e[0] + B[7]*e[1];
    B[0]=n0; B[1]=n1; B[2]=n2; B[3]=n3; B[4]=n4; B[5]=n5; B[6]=n6; B[7]=n7;
}

// ---------------------------------------------------------------------------
// Setup kernels
// ---------------------------------------------------------------------------
__global__ void unpack_kernel(const float* __restrict__ in) {
    // in: [B][3K]; produce time-major scaled/negated arrays:
    //   ls1, lp2 (kept for the interleaved gather), S1/D1, and G1 init (la=0).
    __shared__ float tile[3][32][33];
    int t0 = blockIdx.x * 32;
    int b0 = blockIdx.y * 32;
    int tid = threadIdx.x;
    for (int e = tid; e < 32 * 96; e += 256) {
        int db  = e / 96;
        int off = e % 96;
        float v = in[(size_t)(b0 + db) * (3 * Kc) + 3 * t0 + off];
        tile[off % 3][off / 3][db] = -SCALEF * v;
    }
    __syncthreads();
    for (int e = tid; e < 1024; e += 256) {
        int tt = e >> 5, bb = e & 31;
        int idx = (t0 + tt) * Bc + b0 + bb;
        float vls = tile[0][tt][bb];
        float vp1 = tile[1][tt][bb];
        float vp2 = tile[2][tt][bb];
        float s1 = vls + vp1, d1 = vls - vp1;
        g_ls1[idx] = vls;
        g_lp2[idx] = vp2;
        g_S1[idx]  = s1;
        g_D1[idx]  = d1;
        g_G1[idx]  = make_float2(s1, d1);     // la = 0 for iteration 0
    }
}

__global__ void build_inv_kernel(const int* __restrict__ perm) {
    int j = blockIdx.x * 256 + threadIdx.x;
    if (j < Kc) g_inv[perm[j]] = j;
}

__global__ void gather2_kernel(const int* __restrict__ perm) {
    // S2[j][b] = ls1[perm[j]][b] + lp2[j][b];  D2 = ls1[perm[j]][b] - lp2[j][b]
    int b  = threadIdx.x;
    int j0 = blockIdx.x * 8;
    #pragma unroll
    for (int r = 0; r < 8; ++r) {
        int j = j0 + r;
        float vls = g_ls1[perm[j] * Bc + b];
        float vlp = g_lp2[j * Bc + b];
        g_S2[j * Bc + b] = vls + vlp;
        g_D2[j * Bc + b] = vls - vlp;
    }
}

// ---------------------------------------------------------------------------
// Fused BCJR pass, two warps per block (warp0 = backward, warp1 = forward).
//   dec==0: reads G1, writes G2[inv[t]] from (S2,D2) + extrinsic
//   dec==1: reads G2, writes G1[perm[t]] from (S1,D1) + extrinsic
//   last!=0: also store lpost' (time-major) for the final output transpose.
// ---------------------------------------------------------------------------
__global__ void __launch_bounds__(64) bcjr_pass(int dec, const int* __restrict__ perm, int last) {
    // beta_{t+1} per (t_rel, lane): 8 states as 4 half2 packed in one uint4.
    __shared__ uint4 sbeta[Lc][32];

    const float2* __restrict__ G  = dec ? g_G2 : g_G1;
    float2* __restrict__ Gout     = dec ? g_G1 : g_G2;
    const float* __restrict__ So  = dec ? g_S1 : g_S2;
    const float* __restrict__ Do  = dec ? g_D1 : g_D2;
    const int* __restrict__ map   = dec ? perm : g_inv;

    const int lane = threadIdx.x & 31;
    const int wid  = threadIdx.x >> 5;
    const int b    = blockIdx.y * 32 + lane;
    const int c    = blockIdx.x;
    const int t_lo = c * Lc;
    const int t_sh = t_lo + Lc - 1;

    if (wid == 0) {
        // ---------------- backward warp ----------------
        int t_hi = t_sh + Wc;
        if (t_hi > Kc - 1) t_hi = Kc - 1;   // c==191: 0 warmup (uniform == exact beta_K)

        float B[8];
        #pragma unroll
        for (int s = 0; s < 8; ++s) B[s] = 0.125f;

        // warmup: pairs, normalize once per pair (step count is 32 or 0)
        for (int t = t_hi; t > t_sh; t -= 2) {
            float2 ga = G[t * Bc + b];
            float2 gb = G[(t - 1) * Bc + b];
            float e[4];
            weights(ga, e);
            bwd_step(e, B);
            weights(gb, e);
            bwd_step(e, B);
            norm8(B);
        }
        // main region: store normalized beta_{t+1}, then step+norm each step
        float2 gcur = G[t_sh * Bc + b];
        #pragma unroll 2
        for (int t = t_sh; t >= t_lo; --t) {
            float2 gnext = (t > t_lo) ? G[(t - 1) * Bc + b] : make_float2(0.f, 0.f);

            __half2 h01 = __floats2half2_rn(B[0], B[1]);
            __half2 h23 = __floats2half2_rn(B[2], B[3]);
            __half2 h45 = __floats2half2_rn(B[4], B[5]);
            __half2 h67 = __floats2half2_rn(B[6], B[7]);
            uint4 pk;
            pk.x = reinterpret_cast<unsigned&>(h01);
            pk.y = reinterpret_cast<unsigned&>(h23);
            pk.z = reinterpret_cast<unsigned&>(h45);
            pk.w = reinterpret_cast<unsigned&>(h67);
            sbeta[t - t_lo][lane] = pk;

            float e[4];
            weights(gcur, e);
            bwd_step(e, B);
            norm8(B);
            gcur = gnext;
        }
    } else {
        // ---------------- forward warp: warmup (concurrent with bwd) -------
        int t0 = t_lo - Wc; if (t0 < 0) t0 = 0;
        float A[8];
        if (t0 == 0) {                       // exact init: state 0
            #pragma unroll
            for (int s = 0; s < 8; ++s) A[s] = 0.0f;
            A[0] = 1.0f;
        } else {
            #pragma unroll
            for (int s = 0; s < 8; ++s) A[s] = 0.125f;
        }
        for (int t = t0; t < t_lo; t += 2) { // step count is 32 or 0
            float2 ga = G[t * Bc + b];
            float2 gb = G[(t + 1) * Bc + b];
            float e[4];
            weights(ga, e);
            fwd_step(e, A);
            weights(gb, e);
            fwd_step(e, A);
            norm8(A);
        }
        __syncthreads();                     // wait for sbeta

        // ---------------- forward main + posterior + G scatter -------------
        #pragma unroll 2
        for (int t = t_lo; t <= t_sh; ++t) {
            float2 g = G[t * Bc + b];
            int row  = map[t];
            float so = So[row * Bc + b];
            float dv = Do[row * Bc + b];
            float e[4];
            weights(g, e);

            uint4 pk = sbeta[t - t_lo][lane];
            float2 q01 = __half22float2(reinterpret_cast<__half2&>(pk.x));
            float2 q23 = __half22float2(reinterpret_cast<__half2&>(pk.y));
            float2 q45 = __half22float2(reinterpret_cast<__half2&>(pk.z));
            float2 q67 = __half22float2(reinterpret_cast<__half2&>(pk.w));

            // u_k = sum_s alpha[s] * w(s,u=k) * beta_{t+1}[nxt(s,k)]
            float u0 = e[0] * (A[0]*q01.x + A[1]*q45.x + A[6]*q67.y + A[7]*q23.y)
                     + e[2] * (A[2]*q45.y + A[3]*q01.y + A[4]*q23.x + A[5]*q67.x);
            float u1 = e[1] * (A[0]*q45.x + A[1]*q01.x + A[6]*q23.y + A[7]*q67.y)
                     + e[3] * (A[2]*q01.y + A[3]*q45.y + A[4]*q67.x + A[5]*q23.x);
            float lps = 0.5f * (lg2f(fmaxf(u0, 1e-30f)) - lg2f(fmaxf(u1, 1e-30f)));

            // extrinsic: lps - (la'+ls') = lps - (g0+g1)/2
            float ext = lps - 0.5f * (g.x + g.y);
            float gx  = fminf(fmaxf(so + ext, -GCLAMP), GCLAMP);
            float gy  = fminf(fmaxf(dv + ext, -GCLAMP), GCLAMP);
            Gout[row * Bc + b] = make_float2(gx, gy);
            if (last) g_lpost[t * Bc + b] = lps;

            fwd_step(e, A);
            if ((t - t_lo) & 1) norm8(A);    // normalize every 2nd step
        }
        return;
    }
    __syncthreads();   // bwd warp arrives here after filling sbeta
}

// ---------------------------------------------------------------------------
// Output: out[b][i] = -2*ln2 * lpost'[inv[i]][b]
// ---------------------------------------------------------------------------
__global__ void output_kernel(float* __restrict__ out) {
    __shared__ float tile[32][33];
    int i0 = blockIdx.x * 32, b0 = blockIdx.y * 32;
    int tid = threadIdx.x;
    for (int e = tid; e < 1024; e += 256) {
        int ii = e >> 5, bb = e & 31;
        tile[ii][bb] = OUTSCALE * g_lpost[g_inv[i0 + ii] * Bc + b0 + bb];
    }
    __syncthreads();
    for (int e = tid; e < 1024; e += 256) {
        int bb = e >> 5, ii = e & 31;
        out[(size_t)(b0 + bb) * Kc + i0 + ii] = tile[ii][bb];
    }
}

// ---------------------------------------------------------------------------
extern "C" void kernel_launch(void* const* d_in, const int* in_sizes, int n_in,
                              void* d_out, int out_size) {
    const float* in  = (const float*)d_in[0];
    const int* perm  = (const int*)d_in[1];
    float* out       = (float*)d_out;

    dim3 upg(Kc / 32, Bc / 32);
    unpack_kernel<<<upg, 256>>>(in);
    build_inv_kernel<<<Kc / 256, 256>>>(perm);
    gather2_kernel<<<Kc / 8, 256>>>(perm);

    dim3 bg(Cc, Bc / 32);   // 192 x 8 blocks, 2 warps each -> 3072 warps
    for (int it = 0; it < 6; ++it) {
        bcjr_pass<<<bg, 64>>>(0, perm, 0);
        bcjr_pass<<<bg, 64>>>(1, perm, (it == 5) ? 1 : 0);
    }

    dim3 og(Kc / 32, Bc / 32);
    output_kernel<<<og, 256>>>(out);
}

// round 10
// speedup vs baseline: 1.4924x; 1.0962x over previous
#include <cuda_runtime.h>
#include <cuda_bf16.h>
#include <cuda_fp16.h>

// ---------------------------------------------------------------------------
// Turbo decoder (linear-domain BCJR in log2 units), 8-state RSC,
// B=256, K=6144, 6 iterations. Sliding-window (L=32, W=32).
// Branch metrics pre-combined: G[t][b] = (g0', g1') float2. Each pass reads
// one float2 per step and writes the NEXT pass's G through the interleaver
// using iteration-invariant SD = (ls'+lp', ls'-lp').
// Per chunk: 64-thread block, balanced two-warp schedule:
//   warp0: bwd warmup + beta(upper)->SMEM | bar | beta(lower)->SMEM +
//          posteriors for the LOWER half (parallel, from SMEM alpha+beta)
//   warp1: fwd warmup + alpha(lower)->SMEM | bar | fwd upper walk with
//          inline posteriors for the UPPER half
// ---------------------------------------------------------------------------

constexpr int Kc = 6144;
constexpr int Bc = 256;
constexpr int Lc = 32;
constexpr int Wc = 32;
constexpr int Cc = Kc / Lc;           // 192 chunks
constexpr int Hc = Lc / 2;            // 16
constexpr float SCALEF   = 0.7213475204444817f;   // 0.5*log2(e)
constexpr float OUTSCALE = -1.3862943611198906f;  // -2*ln2  (undo SCALEF, negate)
constexpr float GCLAMP   = 60.0f;                 // log2-unit branch clamp

// Static device scratch (no allocations anywhere).
__device__ float  g_ls1[Kc * Bc];     // scaled, negated systematic (dec1 order)
__device__ float  g_lp2[Kc * Bc];     // scaled, negated parity 2 (dec2 order)
__device__ float2 g_SD1[Kc * Bc];     // (ls1'+lp1', ls1'-lp1')
__device__ float2 g_SD2[Kc * Bc];     // (ls2'+lp2', ls2'-lp2')
__device__ float2 g_G1[Kc * Bc];      // branch metrics for decoder 1
__device__ float2 g_G2[Kc * Bc];      // branch metrics for decoder 2
__device__ float  g_lpost[Kc * Bc];
__device__ int    g_inv[Kc];

__device__ __forceinline__ float ex2f(float x) {
    float y; asm("ex2.approx.ftz.f32 %0, %1;" : "=f"(y) : "f"(x)); return y;
}
__device__ __forceinline__ float lg2f(float x) {
    float y; asm("lg2.approx.ftz.f32 %0, %1;" : "=f"(y) : "f"(x)); return y;
}

// r = 2^-(ilogb(s)) : exponent-field trick, no MUFU.
__device__ __forceinline__ float norm_scale(float s) {
    return __uint_as_float(0x7F000000u - (__float_as_uint(s) & 0x7F800000u));
}

__device__ __forceinline__ void weights(float2 g, float (&e)[4]) {
    e[0] = ex2f(g.x);  e[1] = ex2f(-g.x);   // e0p, e0n
    e[2] = ex2f(g.y);  e[3] = ex2f(-g.y);   // e1p, e1n
}

// Trellis (G0=(1,0,1,1), G1=(1,1,0,1), MU=3):
//   weight(s,u=0) = e0p for s in {0,1,6,7}, e1p for s in {2,3,4,5}; u=1 -> e*n.
//   next: 0:(0,4) 1:(4,0) 2:(5,1) 3:(1,5) 4:(2,6) 5:(6,2) 6:(7,3) 7:(3,7)

__device__ __forceinline__ void norm8(float (&v)[8]) {
    float s = ((v[0]+v[1])+(v[2]+v[3])) + ((v[4]+v[5])+(v[6]+v[7]));
    float r = norm_scale(s);
    #pragma unroll
    for (int i = 0; i < 8; ++i) v[i] *= r;
}

__device__ __forceinline__ void fwd_step(const float (&e)[4], float (&a)[8]) {
    float n0 = a[0]*e[0] + a[1]*e[1];
    float n4 = a[0]*e[1] + a[1]*e[0];
    float n5 = a[2]*e[2] + a[3]*e[3];
    float n1 = a[2]*e[3] + a[3]*e[2];
    float n2 = a[4]*e[2] + a[5]*e[3];
    float n6 = a[4]*e[3] + a[5]*e[2];
    float n7 = a[6]*e[0] + a[7]*e[1];
    float n3 = a[6]*e[1] + a[7]*e[0];
    a[0]=n0; a[1]=n1; a[2]=n2; a[3]=n3; a[4]=n4; a[5]=n5; a[6]=n6; a[7]=n7;
}

__device__ __forceinline__ void bwd_step(const float (&e)[4], float (&B)[8]) {
    float n0 = B[0]*e[0] + B[4]*e[1];
    float n1 = B[4]*e[0] + B[0]*e[1];
    float n2 = B[5]*e[2] + B[1]*e[3];
    float n3 = B[1]*e[2] + B[5]*e[3];
    float n4 = B[2]*e[2] + B[6]*e[3];
    float n5 = B[6]*e[2] + B[2]*e[3];
    float n6 = B[7]*e[0] + B[3]*e[1];
    float n7 = B[3]*e[0] + B[7]*e[1];
    B[0]=n0; B[1]=n1; B[2]=n2; B[3]=n3; B[4]=n4; B[5]=n5; B[6]=n6; B[7]=n7;
}

__device__ __forceinline__ uint4 pack8(const float (&v)[8]) {
    __half2 h01 = __floats2half2_rn(v[0], v[1]);
    __half2 h23 = __floats2half2_rn(v[2], v[3]);
    __half2 h45 = __floats2half2_rn(v[4], v[5]);
    __half2 h67 = __floats2half2_rn(v[6], v[7]);
    uint4 pk;
    pk.x = *reinterpret_cast<unsigned*>(&h01);
    pk.y = *reinterpret_cast<unsigned*>(&h23);
    pk.z = *reinterpret_cast<unsigned*>(&h45);
    pk.w = *reinterpret_cast<unsigned*>(&h67);
    return pk;
}

__device__ __forceinline__ void unpack8(uint4 pk, float (&v)[8]) {
    float2 q01 = __half22float2(*reinterpret_cast<__half2*>(&pk.x));
    float2 q23 = __half22float2(*reinterpret_cast<__half2*>(&pk.y));
    float2 q45 = __half22float2(*reinterpret_cast<__half2*>(&pk.z));
    float2 q67 = __half22float2(*reinterpret_cast<__half2*>(&pk.w));
    v[0]=q01.x; v[1]=q01.y; v[2]=q23.x; v[3]=q23.y;
    v[4]=q45.x; v[5]=q45.y; v[6]=q67.x; v[7]=q67.y;
}

// u_k = sum_s alpha[s] * w(s,u=k) * beta_{t+1}[nxt(s,k)]
__device__ __forceinline__ float posterior8(const float (&A)[8], const float (&v)[8],
                                            const float (&e)[4]) {
    float u0 = e[0] * (A[0]*v[0] + A[1]*v[4] + A[6]*v[7] + A[7]*v[3])
             + e[2] * (A[2]*v[5] + A[3]*v[1] + A[4]*v[2] + A[5]*v[6]);
    float u1 = e[1] * (A[0]*v[4] + A[1]*v[0] + A[6]*v[3] + A[7]*v[7])
             + e[3] * (A[2]*v[1] + A[3]*v[5] + A[4]*v[6] + A[5]*v[2]);
    return 0.5f * (lg2f(fmaxf(u0, 1e-30f)) - lg2f(fmaxf(u1, 1e-30f)));
}

// ---------------------------------------------------------------------------
// Setup kernels
// ---------------------------------------------------------------------------
__global__ void unpack_kernel(const float* __restrict__ in) {
    __shared__ float tile[3][32][33];
    int t0 = blockIdx.x * 32;
    int b0 = blockIdx.y * 32;
    int tid = threadIdx.x;
    for (int e = tid; e < 32 * 96; e += 256) {
        int db  = e / 96;
        int off = e % 96;
        float v = in[(size_t)(b0 + db) * (3 * Kc) + 3 * t0 + off];
        tile[off % 3][off / 3][db] = -SCALEF * v;
    }
    __syncthreads();
    for (int e = tid; e < 1024; e += 256) {
        int tt = e >> 5, bb = e & 31;
        int idx = (t0 + tt) * Bc + b0 + bb;
        float vls = tile[0][tt][bb];
        float vp1 = tile[1][tt][bb];
        float vp2 = tile[2][tt][bb];
        float s1 = vls + vp1, d1 = vls - vp1;
        g_ls1[idx] = vls;
        g_lp2[idx] = vp2;
        g_SD1[idx] = make_float2(s1, d1);
        g_G1[idx]  = make_float2(s1, d1);     // la = 0 for iteration 0
    }
}

__global__ void build_inv_kernel(const int* __restrict__ perm) {
    int j = blockIdx.x * 256 + threadIdx.x;
    if (j < Kc) g_inv[perm[j]] = j;
}

__global__ void gather2_kernel(const int* __restrict__ perm) {
    int b  = threadIdx.x;
    int j0 = blockIdx.x * 8;
    #pragma unroll
    for (int r = 0; r < 8; ++r) {
        int j = j0 + r;
        float vls = g_ls1[perm[j] * Bc + b];
        float vlp = g_lp2[j * Bc + b];
        g_SD2[j * Bc + b] = make_float2(vls + vlp, vls - vlp);
    }
}

// ---------------------------------------------------------------------------
// Fused balanced BCJR pass.
//   dec==0: reads G1, writes G2[inv[t]] from SD2 + extrinsic
//   dec==1: reads G2, writes G1[perm[t]] from SD1 + extrinsic
//   last!=0: also store lpost' (time-major).
// ---------------------------------------------------------------------------
__global__ void __launch_bounds__(64) bcjr_pass(int dec, const int* __restrict__ perm, int last) {
    __shared__ uint4 sbeta[Lc][32];    // beta_{t+1} at slot t - t_lo  (16 KB)
    __shared__ uint4 salpha[Hc][32];   // alpha_t   at slot t - t_lo   (8 KB)

    const float2* __restrict__ G  = dec ? g_G2 : g_G1;
    float2* __restrict__ Gout     = dec ? g_G1 : g_G2;
    const float2* __restrict__ SD = dec ? g_SD1 : g_SD2;
    const int* __restrict__ map   = dec ? perm : g_inv;

    const int lane = threadIdx.x & 31;
    const int wid  = threadIdx.x >> 5;
    const int b    = blockIdx.y * 32 + lane;
    const int c    = blockIdx.x;
    const int t_lo = c * Lc;
    const int t_sh = t_lo + Lc - 1;

    if (wid == 0) {
        // ================= backward warp =================
        float B[8];
        #pragma unroll
        for (int s = 0; s < 8; ++s) B[s] = 0.125f;

        if (c != Cc - 1) {   // warmup 32 steps (batched G loads, MLP=4)
            for (int t = t_sh + Wc; t > t_sh; t -= 4) {
                float2 ga = G[(t    ) * Bc + b];
                float2 gb = G[(t - 1) * Bc + b];
                float2 gc2 = G[(t - 2) * Bc + b];
                float2 gd = G[(t - 3) * Bc + b];
                float e[4];
                weights(ga, e);  bwd_step(e, B);
                weights(gb, e);  bwd_step(e, B);
                norm8(B);
                weights(gc2, e); bwd_step(e, B);
                weights(gd, e);  bwd_step(e, B);
                norm8(B);
            }
        }
        // segment 1: upper half stores (slots 31..16)
        #pragma unroll 4
        for (int t = t_sh; t >= t_lo + Hc; --t) {
            sbeta[t - t_lo][lane] = pack8(B);
            float e[4];
            weights(G[t * Bc + b], e);
            bwd_step(e, B);
            norm8(B);
        }
        __syncthreads();
        // segment 2: lower half stores (slots 15..0); cache G in registers
        float2 gcach[Hc];
        #pragma unroll
        for (int i = Hc - 1; i >= 0; --i) {
            sbeta[i][lane] = pack8(B);
            float2 g = G[(t_lo + i) * Bc + b];
            gcach[i] = g;
            float e[4];
            weights(g, e);
            bwd_step(e, B);
            norm8(B);
        }
        // posteriors for the LOWER half (independent -> parallel loads)
        #pragma unroll 4
        for (int i = 0; i < Hc; ++i) {
            int t = t_lo + i;
            float A[8], v[8], e[4];
            unpack8(salpha[i][lane], A);
            unpack8(sbeta[i][lane], v);
            weights(gcach[i], e);
            float lps = posterior8(A, v, e);
            int row = map[t];
            float2 sd = SD[row * Bc + b];
            float ext = lps - 0.5f * (gcach[i].x + gcach[i].y);
            Gout[row * Bc + b] = make_float2(
                fminf(fmaxf(sd.x + ext, -GCLAMP), GCLAMP),
                fminf(fmaxf(sd.y + ext, -GCLAMP), GCLAMP));
            if (last) g_lpost[t * Bc + b] = lps;
        }
    } else {
        // ================= forward warp =================
        float A[8];
        if (c == 0) {                         // exact init: state 0, no warmup
            #pragma unroll
            for (int s = 0; s < 8; ++s) A[s] = 0.0f;
            A[0] = 1.0f;
        } else {
            #pragma unroll
            for (int s = 0; s < 8; ++s) A[s] = 0.125f;
            for (int t = t_lo - Wc; t < t_lo; t += 4) {
                float2 ga = G[(t    ) * Bc + b];
                float2 gb = G[(t + 1) * Bc + b];
                float2 gc2 = G[(t + 2) * Bc + b];
                float2 gd = G[(t + 3) * Bc + b];
                float e[4];
                weights(ga, e);  fwd_step(e, A);
                weights(gb, e);  fwd_step(e, A);
                norm8(A);
                weights(gc2, e); fwd_step(e, A);
                weights(gd, e);  fwd_step(e, A);
                norm8(A);
            }
        }
        // lower walk: store alpha_t, then step (normalized before each store)
        #pragma unroll 4
        for (int i = 0; i < Hc; ++i) {
            salpha[i][lane] = pack8(A);
            float e[4];
            weights(G[(t_lo + i) * Bc + b], e);
            fwd_step(e, A);
            norm8(A);
        }
        __syncthreads();
        // upper walk with inline posterior
        #pragma unroll 2
        for (int t = t_lo + Hc; t <= t_sh; ++t) {
            float2 g = G[t * Bc + b];
            float e[4], v[8];
            weights(g, e);
            unpack8(sbeta[t - t_lo][lane], v);
            float lps = posterior8(A, v, e);
            int row = map[t];
            float2 sd = SD[row * Bc + b];
            float ext = lps - 0.5f * (g.x + g.y);
            Gout[row * Bc + b] = make_float2(
                fminf(fmaxf(sd.x + ext, -GCLAMP), GCLAMP),
                fminf(fmaxf(sd.y + ext, -GCLAMP), GCLAMP));
            if (last) g_lpost[t * Bc + b] = lps;
            fwd_step(e, A);
            if (t & 1) norm8(A);
        }
    }
}

// ---------------------------------------------------------------------------
// Output: out[b][i] = -2*ln2 * lpost'[inv[i]][b]
// ---------------------------------------------------------------------------
__global__ void output_kernel(float* __restrict__ out) {
    __shared__ float tile[32][33];
    int i0 = blockIdx.x * 32, b0 = blockIdx.y * 32;
    int tid = threadIdx.x;
    for (int e = tid; e < 1024; e += 256) {
        int ii = e >> 5, bb = e & 31;
        tile[ii][bb] = OUTSCALE * g_lpost[g_inv[i0 + ii] * Bc + b0 + bb];
    }
    __syncthreads();
    for (int e = tid; e < 1024; e += 256) {
        int bb = e >> 5, ii = e & 31;
        out[(size_t)(b0 + bb) * Kc + i0 + ii] = tile[ii][bb];
    }
}

// ---------------------------------------------------------------------------
extern "C" void kernel_launch(void* const* d_in, const int* in_sizes, int n_in,
                              void* d_out, int out_size) {
    const float* in  = (const float*)d_in[0];
    const int* perm  = (const int*)d_in[1];
    float* out       = (float*)d_out;

    dim3 upg(Kc / 32, Bc / 32);
    unpack_kernel<<<upg, 256>>>(in);
    build_inv_kernel<<<Kc / 256, 256>>>(perm);
    gather2_kernel<<<Kc / 8, 256>>>(perm);

    dim3 bg(Cc, Bc / 32);   // 192 x 8 blocks, 2 warps each -> 3072 warps
    for (int it = 0; it < 6; ++it) {
        bcjr_pass<<<bg, 64>>>(0, perm, 0);
        bcjr_pass<<<bg, 64>>>(1, perm, (it == 5) ? 1 : 0);
    }

    dim3 og(Kc / 32, Bc / 32);
    output_kernel<<<og, 256>>>(out);
}

// round 11
// speedup vs baseline: 1.5097x; 1.0116x over previous
#include <cuda_runtime.h>
#include <cuda_bf16.h>
#include <cuda_fp16.h>

// ---------------------------------------------------------------------------
// Turbo decoder (linear-domain BCJR in log2 units), 8-state RSC,
// B=256, K=6144, 6 iterations. Sliding-window (L=16, W=32) -> 384 chunks,
// 3072 two-warp blocks per pass (6144 warps) for latency coverage.
// Branch metrics pre-combined: G[t][b] = (g0', g1') float2; passes write the
// next pass's G directly through the interleaver via SD = (ls'+lp', ls'-lp').
// Balanced two-warp schedule per chunk:
//   warp0: bwd warmup + beta(upper)->SMEM | bar | beta(lower)->SMEM +
//          posteriors for the LOWER half (parallel, from SMEM alpha+beta)
//   warp1: fwd warmup + alpha(lower)->SMEM | bar | fwd upper walk with
//          inline posteriors for the UPPER half
// ---------------------------------------------------------------------------

constexpr int Kc = 6144;
constexpr int Bc = 256;
constexpr int Lc = 16;
constexpr int Wc = 32;
constexpr int Cc = Kc / Lc;           // 384 chunks
constexpr int Hc = Lc / 2;            // 8
constexpr float SCALEF   = 0.7213475204444817f;   // 0.5*log2(e)
constexpr float OUTSCALE = -1.3862943611198906f;  // -2*ln2  (undo SCALEF, negate)
constexpr float GCLAMP   = 60.0f;                 // log2-unit branch clamp

// Static device scratch (no allocations anywhere).
__device__ float  g_ls1[Kc * Bc];     // scaled, negated systematic (dec1 order)
__device__ float  g_lp2[Kc * Bc];     // scaled, negated parity 2 (dec2 order)
__device__ float2 g_SD1[Kc * Bc];     // (ls1'+lp1', ls1'-lp1')
__device__ float2 g_SD2[Kc * Bc];     // (ls2'+lp2', ls2'-lp2')
__device__ float2 g_G1[Kc * Bc];      // branch metrics for decoder 1
__device__ float2 g_G2[Kc * Bc];      // branch metrics for decoder 2
__device__ float  g_lpost[Kc * Bc];
__device__ int    g_inv[Kc];

__device__ __forceinline__ float ex2f(float x) {
    float y; asm("ex2.approx.ftz.f32 %0, %1;" : "=f"(y) : "f"(x)); return y;
}
__device__ __forceinline__ float lg2f(float x) {
    float y; asm("lg2.approx.ftz.f32 %0, %1;" : "=f"(y) : "f"(x)); return y;
}

// r = 2^-(ilogb(s)) : exponent-field trick, no MUFU.
__device__ __forceinline__ float norm_scale(float s) {
    return __uint_as_float(0x7F000000u - (__float_as_uint(s) & 0x7F800000u));
}

__device__ __forceinline__ void weights(float2 g, float (&e)[4]) {
    e[0] = ex2f(g.x);  e[1] = ex2f(-g.x);   // e0p, e0n
    e[2] = ex2f(g.y);  e[3] = ex2f(-g.y);   // e1p, e1n
}

// Trellis (G0=(1,0,1,1), G1=(1,1,0,1), MU=3):
//   weight(s,u=0) = e0p for s in {0,1,6,7}, e1p for s in {2,3,4,5}; u=1 -> e*n.
//   next: 0:(0,4) 1:(4,0) 2:(5,1) 3:(1,5) 4:(2,6) 5:(6,2) 6:(7,3) 7:(3,7)

__device__ __forceinline__ void norm8(float (&v)[8]) {
    float s = ((v[0]+v[1])+(v[2]+v[3])) + ((v[4]+v[5])+(v[6]+v[7]));
    float r = norm_scale(s);
    #pragma unroll
    for (int i = 0; i < 8; ++i) v[i] *= r;
}

__device__ __forceinline__ void fwd_step(const float (&e)[4], float (&a)[8]) {
    float n0 = a[0]*e[0] + a[1]*e[1];
    float n4 = a[0]*e[1] + a[1]*e[0];
    float n5 = a[2]*e[2] + a[3]*e[3];
    float n1 = a[2]*e[3] + a[3]*e[2];
    float n2 = a[4]*e[2] + a[5]*e[3];
    float n6 = a[4]*e[3] + a[5]*e[2];
    float n7 = a[6]*e[0] + a[7]*e[1];
    float n3 = a[6]*e[1] + a[7]*e[0];
    a[0]=n0; a[1]=n1; a[2]=n2; a[3]=n3; a[4]=n4; a[5]=n5; a[6]=n6; a[7]=n7;
}

__device__ __forceinline__ void bwd_step(const float (&e)[4], float (&B)[8]) {
    float n0 = B[0]*e[0] + B[4]*e[1];
    float n1 = B[4]*e[0] + B[0]*e[1];
    float n2 = B[5]*e[2] + B[1]*e[3];
    float n3 = B[1]*e[2] + B[5]*e[3];
    float n4 = B[2]*e[2] + B[6]*e[3];
    float n5 = B[6]*e[2] + B[2]*e[3];
    float n6 = B[7]*e[0] + B[3]*e[1];
    float n7 = B[3]*e[0] + B[7]*e[1];
    B[0]=n0; B[1]=n1; B[2]=n2; B[3]=n3; B[4]=n4; B[5]=n5; B[6]=n6; B[7]=n7;
}

__device__ __forceinline__ uint4 pack8(const float (&v)[8]) {
    __half2 h01 = __floats2half2_rn(v[0], v[1]);
    __half2 h23 = __floats2half2_rn(v[2], v[3]);
    __half2 h45 = __floats2half2_rn(v[4], v[5]);
    __half2 h67 = __floats2half2_rn(v[6], v[7]);
    uint4 pk;
    pk.x = *reinterpret_cast<unsigned*>(&h01);
    pk.y = *reinterpret_cast<unsigned*>(&h23);
    pk.z = *reinterpret_cast<unsigned*>(&h45);
    pk.w = *reinterpret_cast<unsigned*>(&h67);
    return pk;
}

__device__ __forceinline__ void unpack8(uint4 pk, float (&v)[8]) {
    float2 q01 = __half22float2(*reinterpret_cast<__half2*>(&pk.x));
    float2 q23 = __half22float2(*reinterpret_cast<__half2*>(&pk.y));
    float2 q45 = __half22float2(*reinterpret_cast<__half2*>(&pk.z));
    float2 q67 = __half22float2(*reinterpret_cast<__half2*>(&pk.w));
    v[0]=q01.x; v[1]=q01.y; v[2]=q23.x; v[3]=q23.y;
    v[4]=q45.x; v[5]=q45.y; v[6]=q67.x; v[7]=q67.y;
}

// u_k = sum_s alpha[s] * w(s,u=k) * beta_{t+1}[nxt(s,k)]
__device__ __forceinline__ float posterior8(const float (&A)[8], const float (&v)[8],
                                            const float (&e)[4]) {
    float u0 = e[0] * (A[0]*v[0] + A[1]*v[4] + A[6]*v[7] + A[7]*v[3])
             + e[2] * (A[2]*v[5] + A[3]*v[1] + A[4]*v[2] + A[5]*v[6]);
    float u1 = e[1] * (A[0]*v[4] + A[1]*v[0] + A[6]*v[3] + A[7]*v[7])
             + e[3] * (A[2]*v[1] + A[3]*v[5] + A[4]*v[6] + A[5]*v[2]);
    return 0.5f * (lg2f(fmaxf(u0, 1e-30f)) - lg2f(fmaxf(u1, 1e-30f)));
}

// ---------------------------------------------------------------------------
// Setup kernels
// ---------------------------------------------------------------------------
__global__ void unpack_kernel(const float* __restrict__ in) {
    __shared__ float tile[3][32][33];
    int t0 = blockIdx.x * 32;
    int b0 = blockIdx.y * 32;
    int tid = threadIdx.x;
    for (int e = tid; e < 32 * 96; e += 256) {
        int db  = e / 96;
        int off = e % 96;
        float v = in[(size_t)(b0 + db) * (3 * Kc) + 3 * t0 + off];
        tile[off % 3][off / 3][db] = -SCALEF * v;
    }
    __syncthreads();
    for (int e = tid; e < 1024; e += 256) {
        int tt = e >> 5, bb = e & 31;
        int idx = (t0 + tt) * Bc + b0 + bb;
        float vls = tile[0][tt][bb];
        float vp1 = tile[1][tt][bb];
        float vp2 = tile[2][tt][bb];
        float s1 = vls + vp1, d1 = vls - vp1;
        g_ls1[idx] = vls;
        g_lp2[idx] = vp2;
        g_SD1[idx] = make_float2(s1, d1);
        g_G1[idx]  = make_float2(s1, d1);     // la = 0 for iteration 0
    }
}

__global__ void build_inv_kernel(const int* __restrict__ perm) {
    int j = blockIdx.x * 256 + threadIdx.x;
    if (j < Kc) g_inv[perm[j]] = j;
}

__global__ void gather2_kernel(const int* __restrict__ perm) {
    int b  = threadIdx.x;
    int j0 = blockIdx.x * 8;
    #pragma unroll
    for (int r = 0; r < 8; ++r) {
        int j = j0 + r;
        float vls = g_ls1[perm[j] * Bc + b];
        float vlp = g_lp2[j * Bc + b];
        g_SD2[j * Bc + b] = make_float2(vls + vlp, vls - vlp);
    }
}

// ---------------------------------------------------------------------------
// Fused balanced BCJR pass (L=16 chunks).
//   dec==0: reads G1, writes G2[inv[t]] from SD2 + extrinsic
//   dec==1: reads G2, writes G1[perm[t]] from SD1 + extrinsic
//   last!=0: also store lpost' (time-major).
// ---------------------------------------------------------------------------
__global__ void __launch_bounds__(64, 12) bcjr_pass(int dec, const int* __restrict__ perm, int last) {
    __shared__ uint4 sbeta[Lc][32];    // beta_{t+1} at slot t - t_lo  (8 KB)
    __shared__ uint4 salpha[Hc][32];   // alpha_t   at slot t - t_lo   (4 KB)

    const float2* __restrict__ G  = dec ? g_G2 : g_G1;
    float2* __restrict__ Gout     = dec ? g_G1 : g_G2;
    const float2* __restrict__ SD = dec ? g_SD1 : g_SD2;
    const int* __restrict__ map   = dec ? perm : g_inv;

    const int lane = threadIdx.x & 31;
    const int wid  = threadIdx.x >> 5;
    const int b    = blockIdx.y * 32 + lane;
    const int c    = blockIdx.x;
    const int t_lo = c * Lc;
    const int t_sh = t_lo + Lc - 1;

    if (wid == 0) {
        // ================= backward warp =================
        float B[8];
        #pragma unroll
        for (int s = 0; s < 8; ++s) B[s] = 0.125f;

        // warmup: length is 32, 16, or 0 (always a multiple of 4); uniform
        // init at t_hi = Kc-1 equals the exact beta_K.
        int t_hi = t_sh + Wc;
        if (t_hi > Kc - 1) t_hi = Kc - 1;
        for (int t = t_hi; t > t_sh; t -= 4) {
            float2 ga = G[(t    ) * Bc + b];
            float2 gb = G[(t - 1) * Bc + b];
            float2 gc2 = G[(t - 2) * Bc + b];
            float2 gd = G[(t - 3) * Bc + b];
            float e[4];
            weights(ga, e);  bwd_step(e, B);
            weights(gb, e);  bwd_step(e, B);
            norm8(B);
            weights(gc2, e); bwd_step(e, B);
            weights(gd, e);  bwd_step(e, B);
            norm8(B);
        }
        // upper half stores (slots 15..8)
        #pragma unroll
        for (int t2 = t_sh; t2 >= t_lo + Hc; --t2) {
            sbeta[t2 - t_lo][lane] = pack8(B);
            float e[4];
            weights(G[t2 * Bc + b], e);
            bwd_step(e, B);
            norm8(B);
        }
        __syncthreads();
        // lower half stores (slots 7..0)
        #pragma unroll
        for (int i = Hc - 1; i >= 0; --i) {
            sbeta[i][lane] = pack8(B);
            float e[4];
            weights(G[(t_lo + i) * Bc + b], e);
            bwd_step(e, B);
            norm8(B);
        }
        // posteriors for the LOWER half (independent -> parallel loads; G rows
        // are L1-resident from the store loop above)
        #pragma unroll
        for (int i = 0; i < Hc; ++i) {
            int t = t_lo + i;
            float2 g = G[t * Bc + b];
            float A[8], v[8], e[4];
            unpack8(salpha[i][lane], A);
            unpack8(sbeta[i][lane], v);
            weights(g, e);
            float lps = posterior8(A, v, e);
            int row = map[t];
            float2 sd = SD[row * Bc + b];
            float ext = lps - 0.5f * (g.x + g.y);
            Gout[row * Bc + b] = make_float2(
                fminf(fmaxf(sd.x + ext, -GCLAMP), GCLAMP),
                fminf(fmaxf(sd.y + ext, -GCLAMP), GCLAMP));
            if (last) g_lpost[t * Bc + b] = lps;
        }
    } else {
        // ================= forward warp =================
        float A[8];
        int t0 = t_lo - Wc; if (t0 < 0) t0 = 0;
        if (t0 == 0) {                        // exact init: state 0 at t=0
            #pragma unroll
            for (int s = 0; s < 8; ++s) A[s] = 0.0f;
            A[0] = 1.0f;
        } else {
            #pragma unroll
            for (int s = 0; s < 8; ++s) A[s] = 0.125f;
        }
        // warmup: length 32, 16, or 0 (multiple of 4)
        for (int t = t0; t < t_lo; t += 4) {
            float2 ga = G[(t    ) * Bc + b];
            float2 gb = G[(t + 1) * Bc + b];
            float2 gc2 = G[(t + 2) * Bc + b];
            float2 gd = G[(t + 3) * Bc + b];
            float e[4];
            weights(ga, e);  fwd_step(e, A);
            weights(gb, e);  fwd_step(e, A);
            norm8(A);
            weights(gc2, e); fwd_step(e, A);
            weights(gd, e);  fwd_step(e, A);
            norm8(A);
        }
        // lower walk: store alpha_t, then step
        #pragma unroll
        for (int i = 0; i < Hc; ++i) {
            salpha[i][lane] = pack8(A);
            float e[4];
            weights(G[(t_lo + i) * Bc + b], e);
            fwd_step(e, A);
            norm8(A);
        }
        __syncthreads();
        // upper walk with inline posterior
        #pragma unroll
        for (int t = t_lo + Hc; t <= t_sh; ++t) {
            float2 g = G[t * Bc + b];
            float e[4], v[8];
            weights(g, e);
            unpack8(sbeta[t - t_lo][lane], v);
            float lps = posterior8(A, v, e);
            int row = map[t];
            float2 sd = SD[row * Bc + b];
            float ext = lps - 0.5f * (g.x + g.y);
            Gout[row * Bc + b] = make_float2(
                fminf(fmaxf(sd.x + ext, -GCLAMP), GCLAMP),
                fminf(fmaxf(sd.y + ext, -GCLAMP), GCLAMP));
            if (last) g_lpost[t * Bc + b] = lps;
            fwd_step(e, A);
            norm8(A);
        }
    }
}

// ---------------------------------------------------------------------------
// Output: out[b][i] = -2*ln2 * lpost'[inv[i]][b]
// ---------------------------------------------------------------------------
__global__ void output_kernel(float* __restrict__ out) {
    __shared__ float tile[32][33];
    int i0 = blockIdx.x * 32, b0 = blockIdx.y * 32;
    int tid = threadIdx.x;
    for (int e = tid; e < 1024; e += 256) {
        int ii = e >> 5, bb = e & 31;
        tile[ii][bb] = OUTSCALE * g_lpost[g_inv[i0 + ii] * Bc + b0 + bb];
    }
    __syncthreads();
    for (int e = tid; e < 1024; e += 256) {
        int bb = e >> 5, ii = e & 31;
        out[(size_t)(b0 + bb) * Kc + i0 + ii] = tile[ii][bb];
    }
}

// ---------------------------------------------------------------------------
extern "C" void kernel_launch(void* const* d_in, const int* in_sizes, int n_in,
                              void* d_out, int out_size) {
    const float* in  = (const float*)d_in[0];
    const int* perm  = (const int*)d_in[1];
    float* out       = (float*)d_out;

    dim3 upg(Kc / 32, Bc / 32);
    unpack_kernel<<<upg, 256>>>(in);
    build_inv_kernel<<<Kc / 256, 256>>>(perm);
    gather2_kernel<<<Kc / 8, 256>>>(perm);

    dim3 bg(Cc, Bc / 32);   // 384 x 8 blocks, 2 warps each -> 6144 warps
    for (int it = 0; it < 6; ++it) {
        bcjr_pass<<<bg, 64>>>(0, perm, 0);
        bcjr_pass<<<bg, 64>>>(1, perm, (it == 5) ? 1 : 0);
    }

    dim3 og(Kc / 32, Bc / 32);
    output_kernel<<<og, 256>>>(out);
}

// round 12
// speedup vs baseline: 1.8787x; 1.2445x over previous
#include <cuda_runtime.h>
#include <cuda_bf16.h>
#include <cuda_fp16.h>

// ---------------------------------------------------------------------------
// Turbo decoder (linear-domain BCJR in log2 units), 8-state RSC,
// B=256, K=6144, 6 iterations. Sliding-window (L=16, W=16) -> 384 chunks,
// 3072 two-warp blocks per pass (6144 warps).
// Branch metrics pre-combined: G[t][b] = (g0', g1') float2; passes write the
// next pass's G directly through the interleaver via SD = (ls'+lp', ls'-lp').
// Balanced two-warp schedule per chunk:
//   warp0: bwd warmup + beta(upper)->SMEM | bar | beta(lower)->SMEM +
//          posteriors for the LOWER half (parallel, from SMEM alpha+beta)
//   warp1: fwd warmup + alpha(lower)->SMEM | bar | fwd upper walk with
//          inline posteriors for the UPPER half
// ---------------------------------------------------------------------------

constexpr int Kc = 6144;
constexpr int Bc = 256;
constexpr int Lc = 16;
constexpr int Wc = 16;
constexpr int Cc = Kc / Lc;           // 384 chunks
constexpr int Hc = Lc / 2;            // 8
constexpr float SCALEF   = 0.7213475204444817f;   // 0.5*log2(e)
constexpr float OUTSCALE = -1.3862943611198906f;  // -2*ln2  (undo SCALEF, negate)
constexpr float GCLAMP   = 60.0f;                 // log2-unit branch clamp

// Static device scratch (no allocations anywhere).
__device__ float  g_ls1[Kc * Bc];     // scaled, negated systematic (dec1 order)
__device__ float  g_lp2[Kc * Bc];     // scaled, negated parity 2 (dec2 order)
__device__ float2 g_SD1[Kc * Bc];     // (ls1'+lp1', ls1'-lp1')
__device__ float2 g_SD2[Kc * Bc];     // (ls2'+lp2', ls2'-lp2')
__device__ float2 g_G1[Kc * Bc];      // branch metrics for decoder 1
__device__ float2 g_G2[Kc * Bc];      // branch metrics for decoder 2
__device__ float  g_lpost[Kc * Bc];
__device__ int    g_inv[Kc];

__device__ __forceinline__ float ex2f(float x) {
    float y; asm("ex2.approx.ftz.f32 %0, %1;" : "=f"(y) : "f"(x)); return y;
}
__device__ __forceinline__ float lg2f(float x) {
    float y; asm("lg2.approx.ftz.f32 %0, %1;" : "=f"(y) : "f"(x)); return y;
}

// r = 2^-(ilogb(s)) : exponent-field trick, no MUFU.
__device__ __forceinline__ float norm_scale(float s) {
    return __uint_as_float(0x7F000000u - (__float_as_uint(s) & 0x7F800000u));
}

__device__ __forceinline__ void weights(float2 g, float (&e)[4]) {
    e[0] = ex2f(g.x);  e[1] = ex2f(-g.x);   // e0p, e0n
    e[2] = ex2f(g.y);  e[3] = ex2f(-g.y);   // e1p, e1n
}

// Trellis (G0=(1,0,1,1), G1=(1,1,0,1), MU=3):
//   weight(s,u=0) = e0p for s in {0,1,6,7}, e1p for s in {2,3,4,5}; u=1 -> e*n.
//   next: 0:(0,4) 1:(4,0) 2:(5,1) 3:(1,5) 4:(2,6) 5:(6,2) 6:(7,3) 7:(3,7)

__device__ __forceinline__ void norm8(float (&v)[8]) {
    float s = ((v[0]+v[1])+(v[2]+v[3])) + ((v[4]+v[5])+(v[6]+v[7]));
    float r = norm_scale(s);
    #pragma unroll
    for (int i = 0; i < 8; ++i) v[i] *= r;
}

__device__ __forceinline__ void fwd_step(const float (&e)[4], float (&a)[8]) {
    float n0 = a[0]*e[0] + a[1]*e[1];
    float n4 = a[0]*e[1] + a[1]*e[0];
    float n5 = a[2]*e[2] + a[3]*e[3];
    float n1 = a[2]*e[3] + a[3]*e[2];
    float n2 = a[4]*e[2] + a[5]*e[3];
    float n6 = a[4]*e[3] + a[5]*e[2];
    float n7 = a[6]*e[0] + a[7]*e[1];
    float n3 = a[6]*e[1] + a[7]*e[0];
    a[0]=n0; a[1]=n1; a[2]=n2; a[3]=n3; a[4]=n4; a[5]=n5; a[6]=n6; a[7]=n7;
}

__device__ __forceinline__ void bwd_step(const float (&e)[4], float (&B)[8]) {
    float n0 = B[0]*e[0] + B[4]*e[1];
    float n1 = B[4]*e[0] + B[0]*e[1];
    float n2 = B[5]*e[2] + B[1]*e[3];
    float n3 = B[1]*e[2] + B[5]*e[3];
    float n4 = B[2]*e[2] + B[6]*e[3];
    float n5 = B[6]*e[2] + B[2]*e[3];
    float n6 = B[7]*e[0] + B[3]*e[1];
    float n7 = B[3]*e[0] + B[7]*e[1];
    B[0]=n0; B[1]=n1; B[2]=n2; B[3]=n3; B[4]=n4; B[5]=n5; B[6]=n6; B[7]=n7;
}

__device__ __forceinline__ uint4 pack8(const float (&v)[8]) {
    __half2 h01 = __floats2half2_rn(v[0], v[1]);
    __half2 h23 = __floats2half2_rn(v[2], v[3]);
    __half2 h45 = __floats2half2_rn(v[4], v[5]);
    __half2 h67 = __floats2half2_rn(v[6], v[7]);
    uint4 pk;
    pk.x = *reinterpret_cast<unsigned*>(&h01);
    pk.y = *reinterpret_cast<unsigned*>(&h23);
    pk.z = *reinterpret_cast<unsigned*>(&h45);
    pk.w = *reinterpret_cast<unsigned*>(&h67);
    return pk;
}

__device__ __forceinline__ void unpack8(uint4 pk, float (&v)[8]) {
    float2 q01 = __half22float2(*reinterpret_cast<__half2*>(&pk.x));
    float2 q23 = __half22float2(*reinterpret_cast<__half2*>(&pk.y));
    float2 q45 = __half22float2(*reinterpret_cast<__half2*>(&pk.z));
    float2 q67 = __half22float2(*reinterpret_cast<__half2*>(&pk.w));
    v[0]=q01.x; v[1]=q01.y; v[2]=q23.x; v[3]=q23.y;
    v[4]=q45.x; v[5]=q45.y; v[6]=q67.x; v[7]=q67.y;
}

// u_k = sum_s alpha[s] * w(s,u=k) * beta_{t+1}[nxt(s,k)]
__device__ __forceinline__ float posterior8(const float (&A)[8], const float (&v)[8],
                                            const float (&e)[4]) {
    float u0 = e[0] * (A[0]*v[0] + A[1]*v[4] + A[6]*v[7] + A[7]*v[3])
             + e[2] * (A[2]*v[5] + A[3]*v[1] + A[4]*v[2] + A[5]*v[6]);
    float u1 = e[1] * (A[0]*v[4] + A[1]*v[0] + A[6]*v[3] + A[7]*v[7])
             + e[3] * (A[2]*v[1] + A[3]*v[5] + A[4]*v[6] + A[5]*v[2]);
    return 0.5f * (lg2f(fmaxf(u0, 1e-30f)) - lg2f(fmaxf(u1, 1e-30f)));
}

// ---------------------------------------------------------------------------
// Setup kernels
// ---------------------------------------------------------------------------
__global__ void unpack_kernel(const float* __restrict__ in) {
    __shared__ float tile[3][32][33];
    int t0 = blockIdx.x * 32;
    int b0 = blockIdx.y * 32;
    int tid = threadIdx.x;
    for (int e = tid; e < 32 * 96; e += 256) {
        int db  = e / 96;
        int off = e % 96;
        float v = in[(size_t)(b0 + db) * (3 * Kc) + 3 * t0 + off];
        tile[off % 3][off / 3][db] = -SCALEF * v;
    }
    __syncthreads();
    for (int e = tid; e < 1024; e += 256) {
        int tt = e >> 5, bb = e & 31;
        int idx = (t0 + tt) * Bc + b0 + bb;
        float vls = tile[0][tt][bb];
        float vp1 = tile[1][tt][bb];
        float vp2 = tile[2][tt][bb];
        float s1 = vls + vp1, d1 = vls - vp1;
        g_ls1[idx] = vls;
        g_lp2[idx] = vp2;
        g_SD1[idx] = make_float2(s1, d1);
        g_G1[idx]  = make_float2(s1, d1);     // la = 0 for iteration 0
    }
}

__global__ void build_inv_kernel(const int* __restrict__ perm) {
    int j = blockIdx.x * 256 + threadIdx.x;
    if (j < Kc) g_inv[perm[j]] = j;
}

__global__ void gather2_kernel(const int* __restrict__ perm) {
    int b  = threadIdx.x;
    int j0 = blockIdx.x * 8;
    #pragma unroll
    for (int r = 0; r < 8; ++r) {
        int j = j0 + r;
        float vls = g_ls1[perm[j] * Bc + b];
        float vlp = g_lp2[j * Bc + b];
        g_SD2[j * Bc + b] = make_float2(vls + vlp, vls - vlp);
    }
}

// ---------------------------------------------------------------------------
// Fused balanced BCJR pass (L=16, W=16).
//   dec==0: reads G1, writes G2[inv[t]] from SD2 + extrinsic
//   dec==1: reads G2, writes G1[perm[t]] from SD1 + extrinsic
//   last!=0: also store lpost' (time-major).
// ---------------------------------------------------------------------------
__global__ void __launch_bounds__(64, 12) bcjr_pass(int dec, const int* __restrict__ perm, int last) {
    __shared__ uint4 sbeta[Lc][32];    // beta_{t+1} at slot t - t_lo  (8 KB)
    __shared__ uint4 salpha[Hc][32];   // alpha_t   at slot t - t_lo   (4 KB)

    const float2* __restrict__ G  = dec ? g_G2 : g_G1;
    float2* __restrict__ Gout     = dec ? g_G1 : g_G2;
    const float2* __restrict__ SD = dec ? g_SD1 : g_SD2;
    const int* __restrict__ map   = dec ? perm : g_inv;

    const int lane = threadIdx.x & 31;
    const int wid  = threadIdx.x >> 5;
    const int b    = blockIdx.y * 32 + lane;
    const int c    = blockIdx.x;
    const int t_lo = c * Lc;
    const int t_sh = t_lo + Lc - 1;

    if (wid == 0) {
        // ================= backward warp =================
        float B[8];
        #pragma unroll
        for (int s = 0; s < 8; ++s) B[s] = 0.125f;

        // warmup: length is 16 or 0 (multiple of 4); uniform init at
        // t_hi = Kc-1 equals the exact beta_K.
        int t_hi = t_sh + Wc;
        if (t_hi > Kc - 1) t_hi = Kc - 1;
        for (int t = t_hi; t > t_sh; t -= 4) {
            float2 ga = G[(t    ) * Bc + b];
            float2 gb = G[(t - 1) * Bc + b];
            float2 gc2 = G[(t - 2) * Bc + b];
            float2 gd = G[(t - 3) * Bc + b];
            float e[4];
            weights(ga, e);  bwd_step(e, B);
            weights(gb, e);  bwd_step(e, B);
            norm8(B);
            weights(gc2, e); bwd_step(e, B);
            weights(gd, e);  bwd_step(e, B);
            norm8(B);
        }
        // upper half stores (slots 15..8)
        #pragma unroll
        for (int t2 = t_sh; t2 >= t_lo + Hc; --t2) {
            sbeta[t2 - t_lo][lane] = pack8(B);
            float e[4];
            weights(G[t2 * Bc + b], e);
            bwd_step(e, B);
            norm8(B);
        }
        __syncthreads();
        // lower half stores (slots 7..0)
        #pragma unroll
        for (int i = Hc - 1; i >= 0; --i) {
            sbeta[i][lane] = pack8(B);
            float e[4];
            weights(G[(t_lo + i) * Bc + b], e);
            bwd_step(e, B);
            norm8(B);
        }
        // posteriors for the LOWER half (independent -> parallel loads; G rows
        // are L1-resident from the store loop above)
        #pragma unroll
        for (int i = 0; i < Hc; ++i) {
            int t = t_lo + i;
            float2 g = G[t * Bc + b];
            float A[8], v[8], e[4];
            unpack8(salpha[i][lane], A);
            unpack8(sbeta[i][lane], v);
            weights(g, e);
            float lps = posterior8(A, v, e);
            int row = map[t];
            float2 sd = SD[row * Bc + b];
            float ext = lps - 0.5f * (g.x + g.y);
            Gout[row * Bc + b] = make_float2(
                fminf(fmaxf(sd.x + ext, -GCLAMP), GCLAMP),
                fminf(fmaxf(sd.y + ext, -GCLAMP), GCLAMP));
            if (last) g_lpost[t * Bc + b] = lps;
        }
    } else {
        // ================= forward warp =================
        float A[8];
        int t0 = t_lo - Wc; if (t0 < 0) t0 = 0;
        if (t0 == 0 && c == 0) {              // exact init: state 0 at t=0
            #pragma unroll
            for (int s = 0; s < 8; ++s) A[s] = 0.0f;
            A[0] = 1.0f;
        } else {
            #pragma unroll
            for (int s = 0; s < 8; ++s) A[s] = 0.125f;
            if (t0 == 0) {                    // c==1: warm from exact init
                A[0] = 1.0f;
                #pragma unroll
                for (int s = 1; s < 8; ++s) A[s] = 0.0f;
            }
        }
        // warmup: length 16 or 0 (multiple of 4)
        for (int t = t0; t < t_lo; t += 4) {
            float2 ga = G[(t    ) * Bc + b];
            float2 gb = G[(t + 1) * Bc + b];
            float2 gc2 = G[(t + 2) * Bc + b];
            float2 gd = G[(t + 3) * Bc + b];
            float e[4];
            weights(ga, e);  fwd_step(e, A);
            weights(gb, e);  fwd_step(e, A);
            norm8(A);
            weights(gc2, e); fwd_step(e, A);
            weights(gd, e);  fwd_step(e, A);
            norm8(A);
        }
        // lower walk: store alpha_t, then step
        #pragma unroll
        for (int i = 0; i < Hc; ++i) {
            salpha[i][lane] = pack8(A);
            float e[4];
            weights(G[(t_lo + i) * Bc + b], e);
            fwd_step(e, A);
            norm8(A);
        }
        __syncthreads();
        // upper walk with inline posterior
        #pragma unroll
        for (int t = t_lo + Hc; t <= t_sh; ++t) {
            float2 g = G[t * Bc + b];
            float e[4], v[8];
            weights(g, e);
            unpack8(sbeta[t - t_lo][lane], v);
            float lps = posterior8(A, v, e);
            int row = map[t];
            float2 sd = SD[row * Bc + b];
            float ext = lps - 0.5f * (g.x + g.y);
            Gout[row * Bc + b] = make_float2(
                fminf(fmaxf(sd.x + ext, -GCLAMP), GCLAMP),
                fminf(fmaxf(sd.y + ext, -GCLAMP), GCLAMP));
            if (last) g_lpost[t * Bc + b] = lps;
            fwd_step(e, A);
            norm8(A);
        }
    }
}

// ---------------------------------------------------------------------------
// Output: out[b][i] = -2*ln2 * lpost'[inv[i]][b]
// ---------------------------------------------------------------------------
__global__ void output_kernel(float* __restrict__ out) {
    __shared__ float tile[32][33];
    int i0 = blockIdx.x * 32, b0 = blockIdx.y * 32;
    int tid = threadIdx.x;
    for (int e = tid; e < 1024; e += 256) {
        int ii = e >> 5, bb = e & 31;
        tile[ii][bb] = OUTSCALE * g_lpost[g_inv[i0 + ii] * Bc + b0 + bb];
    }
    __syncthreads();
    for (int e = tid; e < 1024; e += 256) {
        int bb = e >> 5, ii = e & 31;
        out[(size_t)(b0 + bb) * Kc + i0 + ii] = tile[ii][bb];
    }
}

// ---------------------------------------------------------------------------
extern "C" void kernel_launch(void* const* d_in, const int* in_sizes, int n_in,
                              void* d_out, int out_size) {
    const float* in  = (const float*)d_in[0];
    const int* perm  = (const int*)d_in[1];
    float* out       = (float*)d_out;

    dim3 upg(Kc / 32, Bc / 32);
    unpack_kernel<<<upg, 256>>>(in);
    build_inv_kernel<<<Kc / 256, 256>>>(perm);
    gather2_kernel<<<Kc / 8, 256>>>(perm);

    dim3 bg(Cc, Bc / 32);   // 384 x 8 blocks, 2 warps each -> 6144 warps
    for (int it = 0; it < 6; ++it) {
        bcjr_pass<<<bg, 64>>>(0, perm, 0);
        bcjr_pass<<<bg, 64>>>(1, perm, (it == 5) ? 1 : 0);
    }

    dim3 og(Kc / 32, Bc / 32);
    output_kernel<<<og, 256>>>(out);
}